// round 13
// baseline (speedup 1.0000x reference)
#include <cuda_runtime.h>
#include <cstdint>

#define DIM   512
#define BATCH 32
#define TT    2048
#define NBLK  128
#define RTHR  640               // 16 FMA warps + 4 owner warps

// ---------------- device scratch (no allocations allowed) ----------------
__device__ __align__(16) float g_xT[(size_t)TT * DIM * BATCH];  // [t][k4][b][4]
__device__ __align__(16) float g_hbuf[4][DIM * BATCH];          // [k4][b][4]
__device__ unsigned g_flag[NBLK * 8];   // one flag per block, 32B apart

typedef unsigned long long ull;

// ---------------- f32x2 helpers ----------------
__device__ __forceinline__ ull f2fma(ull a, ull b, ull c){
    ull d; asm("fma.rn.f32x2 %0, %1, %2, %3;" : "=l"(d) : "l"(a), "l"(b), "l"(c)); return d;
}
__device__ __forceinline__ float2 upk(ull v){
    float2 f; asm("mov.b64 {%0, %1}, %2;" : "=f"(f.x), "=f"(f.y) : "l"(v)); return f;
}
__device__ __forceinline__ float hadd(ull v){ float2 f = upk(v); return f.x + f.y; }

__device__ __forceinline__ float sigf(float x){ return 1.0f / (1.0f + __expf(-x)); }
__device__ __forceinline__ float tanhfast(float x){
    float e = __expf(2.0f * x);              // inf-safe at both ends
    return 1.0f - 2.0f / (e + 1.0f);
}

// ---------------- scoped sync primitives ----------------
__device__ __forceinline__ void st_release(unsigned* p, unsigned v){
    asm volatile("st.release.gpu.global.u32 [%0], %1;" :: "l"(p), "r"(v) : "memory");
}
__device__ __forceinline__ unsigned ld_acquire(unsigned* p){
    unsigned v;
    asm volatile("ld.acquire.gpu.global.u32 %0, [%1];" : "=r"(v) : "l"(p) : "memory");
    return v;
}
__device__ __forceinline__ void cpa16(unsigned dst, const void* src){
    asm volatile("cp.async.cg.shared.global [%0], [%1], 16;" :: "r"(dst), "l"(src));
}

// =====================================================================
// Kernel 1: transpose x[b][t][k] -> xT[t][k4][b][4]; block 0 inits state.
// =====================================================================
__global__ void __launch_bounds__(256) xt_kernel(const float* __restrict__ x)
{
    if (blockIdx.x == 0){
        int tid = threadIdx.x;
        for (int i = tid; i < DIM * BATCH; i += 256) g_hbuf[0][i] = 0.0f;
        for (int i = tid; i < NBLK; i += 256) g_flag[i * 8] = 0u;
    }
    size_t gidx = (size_t)blockIdx.x * 256 + threadIdx.x;
    int b  = (int)(gidx & 31);
    int k4 = (int)((gidx >> 5) & 127);
    int t  = (int)(gidx >> 12);
    float4 v = *(const float4*)(x + (size_t)b * ((size_t)TT * DIM)
                                  + (size_t)t * DIM + k4 * 4);
    ((float4*)g_xT)[gidx] = v;
}

// =====================================================================
// Kernel 2: fused persistent LSTM, warp-specialized.
// 128 blocks x 640 threads: warps 0-15 = FMA (warp kh owns k-slice
// [kh*32,+32); lane = (bq = l&7, dl = l>>3); 4 gates x 4 batches x
// dim bx*4+dl over 32 k, x-part + h-part into same acc).
// Warps 16-19 = owners/reducers: thread ol = tid-512 -> (pb = ol&31,
// pd = ol>>5); reads 4 gates x 16 partials (shR stride 528 — max col
// 15*33+31 = 526 must fit!), applies nonlinearities, updates c,
// stores h, releases flag. Split barriers: 1 (FMA arrive after STS,
// owners sync) and 2 = GUARD (owners arrive after reduce, FMA sync
// before STS). No __syncthreads in the loop.
// =====================================================================
__global__ void __launch_bounds__(RTHR) lstm_rec_kernel(
    const float* __restrict__ Wih, const float* __restrict__ Whh,
    const float* __restrict__ bih, const float* __restrict__ bhh,
    float* __restrict__ out)
{
    extern __shared__ float sm[];
    float* shW = sm;              // 16384 fl: f4 idx k4*16+rl ; +2048 f4 = Wih
    float* shH = sm + 16384;      // 16384 fl: [k4][b][4]
    float* shX = sm + 32768;      // 16384 fl: [k4][b][4]
    float* shR = sm + 49152;      // 16 rows x 528
    float* shB = sm + 57600;      // 16 biases

    const int tid  = threadIdx.x;
    const int bx   = blockIdx.x;
    const int kh   = tid >> 5;
    const int lane = tid & 31;

    // Load W_hh and W_ih slices into [k4][rl] layout (once, all threads).
    for (int idx = tid; idx < 4096; idx += RTHR){
        int half = idx >> 11;              // 0 = hh, 1 = ih
        int rem  = idx & 2047;
        int rl   = rem >> 7;               // g*4 + dloc
        int k4   = rem & 127;
        int g = rl >> 2, dloc = rl & 3;
        const float* src = (half ? Wih : Whh)
                         + (size_t)(g * DIM + bx * 4 + dloc) * DIM + k4 * 4;
        ((float4*)shW)[half * 2048 + k4 * 16 + rl] = *(const float4*)src;
    }
    if (tid < 16){
        int n = (tid >> 2) * DIM + bx * 4 + (tid & 3);
        shB[tid] = bih[n] + bhh[n];
    }
    __syncthreads();                       // W + biases ready (one-time)

    if (kh < 16){
        // ======================= FMA warps =======================
        const int bq = lane & 7;
        const int dl = lane >> 3;

        const ulonglong2* WH = (const ulonglong2*)shW;
        const ulonglong2* wh0 = WH + kh*128 + 0*4 + dl;
        const ulonglong2* wh1 = WH + kh*128 + 1*4 + dl;
        const ulonglong2* wh2 = WH + kh*128 + 2*4 + dl;
        const ulonglong2* wh3 = WH + kh*128 + 3*4 + dl;
        const ulonglong2* wx0 = wh0 + 2048;
        const ulonglong2* wx1 = wh1 + 2048;
        const ulonglong2* wx2 = wh2 + 2048;
        const ulonglong2* wx3 = wh3 + 2048;
        const ulonglong2* hp = ((const ulonglong2*)shH) + kh * 256 + bq;
        const ulonglong2* xp = ((const ulonglong2*)shX) + kh * 256 + bq;

        const unsigned stH =
            (unsigned)__cvta_generic_to_shared(shH) + (unsigned)(kh * 256 + lane) * 16u;
        const unsigned stX =
            (unsigned)__cvta_generic_to_shared(shX) + (unsigned)(kh * 256 + lane) * 16u;
        const int stg_src = kh * 256 + lane;

        unsigned* pf = &g_flag[(kh * 8 + (lane & 7)) * 8];

        // prologue: stage x for t = 0
        {
            const float4* xs = (const float4*)g_xT + stg_src;
            #pragma unroll
            for (int q = 0; q < 8; q++) cpa16(stX + q * 512u, xs + q * 32);
            asm volatile("cp.async.commit_group;");
        }

        for (int t = 0; t < TT; t++){
            asm volatile("cp.async.wait_group 0;");
            __syncwarp();

            ull acc[4][4];
            #pragma unroll
            for (int g = 0; g < 4; g++)
                #pragma unroll
                for (int j = 0; j < 4; j++) acc[g][j] = 0ULL;

            // ---- x-FMA ----
            #pragma unroll
            for (int i = 0; i < 8; i++){
                ulonglong2 x0 = xp[i * 32];
                ulonglong2 x1 = xp[i * 32 + 8];
                ulonglong2 x2 = xp[i * 32 + 16];
                ulonglong2 x3 = xp[i * 32 + 24];
                ulonglong2 v0 = wx0[i * 16], v1 = wx1[i * 16];
                ulonglong2 v2 = wx2[i * 16], v3 = wx3[i * 16];
                acc[0][0]=f2fma(x0.x,v0.x,acc[0][0]); acc[0][0]=f2fma(x0.y,v0.y,acc[0][0]);
                acc[0][1]=f2fma(x1.x,v0.x,acc[0][1]); acc[0][1]=f2fma(x1.y,v0.y,acc[0][1]);
                acc[0][2]=f2fma(x2.x,v0.x,acc[0][2]); acc[0][2]=f2fma(x2.y,v0.y,acc[0][2]);
                acc[0][3]=f2fma(x3.x,v0.x,acc[0][3]); acc[0][3]=f2fma(x3.y,v0.y,acc[0][3]);
                acc[1][0]=f2fma(x0.x,v1.x,acc[1][0]); acc[1][0]=f2fma(x0.y,v1.y,acc[1][0]);
                acc[1][1]=f2fma(x1.x,v1.x,acc[1][1]); acc[1][1]=f2fma(x1.y,v1.y,acc[1][1]);
                acc[1][2]=f2fma(x2.x,v1.x,acc[1][2]); acc[1][2]=f2fma(x2.y,v1.y,acc[1][2]);
                acc[1][3]=f2fma(x3.x,v1.x,acc[1][3]); acc[1][3]=f2fma(x3.y,v1.y,acc[1][3]);
                acc[2][0]=f2fma(x0.x,v2.x,acc[2][0]); acc[2][0]=f2fma(x0.y,v2.y,acc[2][0]);
                acc[2][1]=f2fma(x1.x,v2.x,acc[2][1]); acc[2][1]=f2fma(x1.y,v2.y,acc[2][1]);
                acc[2][2]=f2fma(x2.x,v2.x,acc[2][2]); acc[2][2]=f2fma(x2.y,v2.y,acc[2][2]);
                acc[2][3]=f2fma(x3.x,v2.x,acc[2][3]); acc[2][3]=f2fma(x3.y,v2.y,acc[2][3]);
                acc[3][0]=f2fma(x0.x,v3.x,acc[3][0]); acc[3][0]=f2fma(x0.y,v3.y,acc[3][0]);
                acc[3][1]=f2fma(x1.x,v3.x,acc[3][1]); acc[3][1]=f2fma(x1.y,v3.y,acc[3][1]);
                acc[3][2]=f2fma(x2.x,v3.x,acc[3][2]); acc[3][2]=f2fma(x2.y,v3.y,acc[3][2]);
                acc[3][3]=f2fma(x3.x,v3.x,acc[3][3]); acc[3][3]=f2fma(x3.y,v3.y,acc[3][3]);
            }

            // ---- prefetch x for t+1 ----
            {
                int tn = (t + 1 < TT) ? (t + 1) : t;
                const float4* xs = (const float4*)g_xT + (size_t)tn * 4096 + stg_src;
                #pragma unroll
                for (int q = 0; q < 8; q++) cpa16(stX + q * 512u, xs + q * 32);
                asm volatile("cp.async.commit_group;");
            }

            // ---- poll my 8 producers, stage h ----
            if (lane < 8){
                while (ld_acquire(pf) < (unsigned)t) { }
            }
            __syncwarp();
            {
                const float4* hs = (const float4*)g_hbuf[t & 3] + stg_src;
                #pragma unroll
                for (int q = 0; q < 8; q++) cpa16(stH + q * 512u, hs + q * 32);
                asm volatile("cp.async.commit_group;");
                asm volatile("cp.async.wait_group 0;");
            }
            __syncwarp();

            // ---- h-FMA into same accumulators ----
            #pragma unroll
            for (int i = 0; i < 8; i++){
                ulonglong2 h0 = hp[i * 32];
                ulonglong2 h1 = hp[i * 32 + 8];
                ulonglong2 h2 = hp[i * 32 + 16];
                ulonglong2 h3 = hp[i * 32 + 24];
                ulonglong2 v0 = wh0[i * 16], v1 = wh1[i * 16];
                ulonglong2 v2 = wh2[i * 16], v3 = wh3[i * 16];
                acc[0][0]=f2fma(h0.x,v0.x,acc[0][0]); acc[0][0]=f2fma(h0.y,v0.y,acc[0][0]);
                acc[0][1]=f2fma(h1.x,v0.x,acc[0][1]); acc[0][1]=f2fma(h1.y,v0.y,acc[0][1]);
                acc[0][2]=f2fma(h2.x,v0.x,acc[0][2]); acc[0][2]=f2fma(h2.y,v0.y,acc[0][2]);
                acc[0][3]=f2fma(h3.x,v0.x,acc[0][3]); acc[0][3]=f2fma(h3.y,v0.y,acc[0][3]);
                acc[1][0]=f2fma(h0.x,v1.x,acc[1][0]); acc[1][0]=f2fma(h0.y,v1.y,acc[1][0]);
                acc[1][1]=f2fma(h1.x,v1.x,acc[1][1]); acc[1][1]=f2fma(h1.y,v1.y,acc[1][1]);
                acc[1][2]=f2fma(h2.x,v1.x,acc[1][2]); acc[1][2]=f2fma(h2.y,v1.y,acc[1][2]);
                acc[1][3]=f2fma(h3.x,v1.x,acc[1][3]); acc[1][3]=f2fma(h3.y,v1.y,acc[1][3]);
                acc[2][0]=f2fma(h0.x,v2.x,acc[2][0]); acc[2][0]=f2fma(h0.y,v2.y,acc[2][0]);
                acc[2][1]=f2fma(h1.x,v2.x,acc[2][1]); acc[2][1]=f2fma(h1.y,v2.y,acc[2][1]);
                acc[2][2]=f2fma(h2.x,v2.x,acc[2][2]); acc[2][2]=f2fma(h2.y,v2.y,acc[2][2]);
                acc[2][3]=f2fma(h3.x,v2.x,acc[2][3]); acc[2][3]=f2fma(h3.y,v2.y,acc[2][3]);
                acc[3][0]=f2fma(h0.x,v3.x,acc[3][0]); acc[3][0]=f2fma(h0.y,v3.y,acc[3][0]);
                acc[3][1]=f2fma(h1.x,v3.x,acc[3][1]); acc[3][1]=f2fma(h1.y,v3.y,acc[3][1]);
                acc[3][2]=f2fma(h2.x,v3.x,acc[3][2]); acc[3][2]=f2fma(h2.y,v3.y,acc[3][2]);
                acc[3][3]=f2fma(h3.x,v3.x,acc[3][3]); acc[3][3]=f2fma(h3.y,v3.y,acc[3][3]);
            }

            // ---- guard: owners have freed shR (arrived long ago) ----
            asm volatile("bar.sync 2, 640;");
            #pragma unroll
            for (int g = 0; g < 4; g++)
                #pragma unroll
                for (int j = 0; j < 4; j++)
                    shR[(g*4 + j) * 528 + kh * 33 + lane] = hadd(acc[g][j]);
            asm volatile("bar.arrive 1, 640;");
        }
    } else {
        // ======================= owner warps =======================
        const int ol = tid - 512;          // 0..127
        const int pb = ol & 31;            // batch
        const int pd = ol >> 5;            // local dim (owner warp id)
        const int dgp = bx * 4 + pd;
        float* outp = out + (size_t)pb * ((size_t)TT * DIM) + dgp;
        const int hwidx = bx * 128 + pb * 4 + pd;
        unsigned* myflag = &g_flag[bx * 8];
        // reduce base: gate g row = g*4 + (pb>>3); col = (pb&7) + 8*pd
        const int rcol = (pb & 7) + 8 * pd;
        const int rrow = pb >> 3;
        const float b0 = shB[0*4 + pd], b1 = shB[1*4 + pd];
        const float b2 = shB[2*4 + pd], b3 = shB[3*4 + pd];

        float cc = 0.0f;
        asm volatile("bar.arrive 2, 640;");    // pre-arm guard for t=0

        for (int t = 0; t < TT; t++){
            asm volatile("bar.sync 1, 640;");  // partials(t) ready

            const float* r0 = shR + (0*4 + rrow) * 528 + rcol;
            const float* r1 = shR + (1*4 + rrow) * 528 + rcol;
            const float* r2 = shR + (2*4 + rrow) * 528 + rcol;
            const float* r3 = shR + (3*4 + rrow) * 528 + rcol;
            float s0 = b0, s1 = b1, s2 = b2, s3 = b3;
            #pragma unroll
            for (int k = 0; k < 16; k++){
                s0 += r0[k * 33]; s1 += r1[k * 33];
                s2 += r2[k * 33]; s3 += r3[k * 33];
            }
            float iv = sigf(s0), fv = sigf(s1), gv = tanhfast(s2), ov = sigf(s3);
            cc = fv * cc + iv * gv;
            float hv = ov * tanhfast(cc);
            g_hbuf[(t + 1) & 3][hwidx] = hv;

            asm volatile("bar.sync 3, 128;");  // owners: h stores done
            if (ol == 0 && t + 1 < TT) st_release(myflag, (unsigned)(t + 1));
            outp[(size_t)t * DIM] = hv;

            asm volatile("bar.arrive 2, 640;");// shR free for step t+1
        }
    }
}

// =====================================================================
extern "C" void kernel_launch(void* const* d_in, const int* in_sizes, int n_in,
                              void* d_out, int out_size)
{
    (void)in_sizes; (void)n_in; (void)out_size;
    const float* x    = (const float*)d_in[0];
    const float* Wih  = (const float*)d_in[1];
    const float* Whh  = (const float*)d_in[2];
    const float* bih  = (const float*)d_in[3];
    const float* bhh  = (const float*)d_in[4];
    float* out = (float*)d_out;

    // 16384 + 16384 + 16384 + 8448 + 16 = 57616 floats = 230464 bytes
    cudaFuncSetAttribute(lstm_rec_kernel,
                         cudaFuncAttributeMaxDynamicSharedMemorySize, 230464);

    xt_kernel<<<(TT * DIM * BATCH / 4) / 256, 256>>>(x);
    lstm_rec_kernel<<<NBLK, RTHR, 230464>>>(Wih, Whh, bih, bhh, out);
}